// round 1
// baseline (speedup 1.0000x reference)
#include <cuda_runtime.h>
#include <math_constants.h>

// Problem constants
#define K_CODES 8192
#define DIM     256
#define TLEN    2048
#define BATCH   16
#define NTOK    32768           // BATCH*TLEN

// Output layout (float32, concatenated in reference-return order)
#define OFF_ZQ    0ull                         // 16*256*2048 = 8388608
#define OFF_IDX   8388608ull                   // 32768
#define OFF_LOSS  8421376ull                   // 1
#define OFF_NEMB  8421377ull                   // 8192*256 = 2097152
#define OFF_NCS   10518529ull                  // 8192
#define OFF_NEA   10526721ull                  // 2097152
#define OFF_UTIL  12623873ull                  // 1

// Scratch (device globals; no allocation allowed)
__device__ float g_esq[K_CODES];
__device__ int   g_idx[NTOK];
__device__ float g_counts[K_CODES];
__device__ float g_sumemb[K_CODES * DIM];
__device__ float g_scal[4];   // [0]=loss partial sum, [1]=n

// ---------------------------------------------------------------------------
// Zero scratch that is accumulated into (must be re-zeroed every launch).
__global__ void k_init() {
    int gid = blockIdx.x * blockDim.x + threadIdx.x;
    if (gid < K_CODES * DIM / 4) {
        ((float4*)g_sumemb)[gid] = make_float4(0.f, 0.f, 0.f, 0.f);
    }
    if (gid < K_CODES) g_counts[gid] = 0.f;
    if (gid < 4) g_scal[gid] = 0.f;
}

// ---------------------------------------------------------------------------
// esq[k] = sum_d embedding[k][d]^2   (one warp per code)
__global__ void k_esq(const float* __restrict__ emb) {
    int warp = (blockIdx.x * blockDim.x + threadIdx.x) >> 5;
    int lane = threadIdx.x & 31;
    const float* row = emb + (size_t)warp * DIM;
    float s = 0.f;
#pragma unroll
    for (int q = 0; q < 8; q++) {
        float v = row[lane + q * 32];
        s = fmaf(v, v, s);
    }
#pragma unroll
    for (int o = 16; o; o >>= 1) s += __shfl_xor_sync(0xFFFFFFFFu, s, o);
    if (lane == 0) g_esq[warp] = s;
}

// ---------------------------------------------------------------------------
// Fused fp32 distance GEMM + argmin.
// Tile: 128 tokens x 128 codes per chunk, K-dim (D=256) in steps of 32.
// Each thread: 8x8 micro-tile. dist = esq[k] - 2 * dot(z, e[k])  (||z||^2 is
// a per-row constant, does not change argmin).
__global__ __launch_bounds__(256, 2)
void k_argmin(const float* __restrict__ z, const float* __restrict__ emb,
              float* __restrict__ out_idx) {
    __shared__ float sm[2 * 32 * 132];      // As[32][132] | Bs[32][132]
    float* As = sm;
    float* Bs = sm + 32 * 132;

    const int tid  = threadIdx.x;
    const int bm0  = blockIdx.x * 128;      // first token of this block
    const int b    = bm0 >> 11;             // token / 2048
    const int t0   = bm0 & 2047;
    const float* zb = z + (size_t)b * DIM * TLEN;   // z_e[b, :, :]

    const int mrow = tid & 15;              // token micro-row   (8 tokens)
    const int ncol = tid >> 4;              // code micro-column (8 codes)

    float bestv[8];
    int   besti[8];
#pragma unroll
    for (int i = 0; i < 8; i++) { bestv[i] = CUDART_INF_F; besti[i] = 0; }

    for (int nc = 0; nc < K_CODES; nc += 128) {
        float acc[8][8];
#pragma unroll
        for (int i = 0; i < 8; i++)
#pragma unroll
            for (int j = 0; j < 8; j++) acc[i][j] = 0.f;

        for (int d0 = 0; d0 < DIM; d0 += 32) {
            __syncthreads();
            // Load A tile: As[d][m], 32x128. z_e[b, d0+row, t0+col] contiguous in col.
#pragma unroll
            for (int l = 0; l < 4; l++) {
                int i4  = tid + l * 256;        // 0..1023 float4 slots
                int row = i4 >> 5;              // d within chunk
                int c4  = i4 & 31;              // col/4
                float4 v = *(const float4*)(zb + (size_t)(d0 + row) * TLEN + t0 + c4 * 4);
                *(float4*)(As + row * 132 + c4 * 4) = v;
            }
            // Load B tile transposed: Bs[d][n]. emb rows are contiguous in d.
#pragma unroll
            for (int l = 0; l < 4; l++) {
                int i4 = tid + l * 256;
                int j  = i4 >> 3;               // code row 0..127
                int d4 = i4 & 7;                // d/4 within chunk
                float4 v = *(const float4*)(emb + (size_t)(nc + j) * DIM + d0 + d4 * 4);
                Bs[(d4 * 4 + 0) * 132 + j] = v.x;
                Bs[(d4 * 4 + 1) * 132 + j] = v.y;
                Bs[(d4 * 4 + 2) * 132 + j] = v.z;
                Bs[(d4 * 4 + 3) * 132 + j] = v.w;
            }
            __syncthreads();

#pragma unroll 4
            for (int dd = 0; dd < 32; dd++) {
                float4 a0 = *(const float4*)(As + dd * 132 + mrow * 8);
                float4 a1 = *(const float4*)(As + dd * 132 + mrow * 8 + 4);
                float4 b0 = *(const float4*)(Bs + dd * 132 + ncol * 8);
                float4 b1 = *(const float4*)(Bs + dd * 132 + ncol * 8 + 4);
                float a[8] = {a0.x, a0.y, a0.z, a0.w, a1.x, a1.y, a1.z, a1.w};
                float bb[8] = {b0.x, b0.y, b0.z, b0.w, b1.x, b1.y, b1.z, b1.w};
#pragma unroll
                for (int i = 0; i < 8; i++)
#pragma unroll
                    for (int j = 0; j < 8; j++)
                        acc[i][j] = fmaf(a[i], bb[j], acc[i][j]);
            }
        }

        // Fold this code chunk into the running argmin (ascending index scan,
        // strict < keeps the first/lowest index on ties).
#pragma unroll
        for (int j = 0; j < 8; j++) {
            int nidx = nc + ncol * 8 + j;
            float eq = g_esq[nidx];
#pragma unroll
            for (int i = 0; i < 8; i++) {
                float dist = eq - 2.0f * acc[i][j];
                if (dist < bestv[i]) { bestv[i] = dist; besti[i] = nidx; }
            }
        }
    }

    // Cross-thread reduction: 16 candidates per token. Reuse smem.
    __syncthreads();
    float* rv = sm;                         // [128][16]
    int*   ri = (int*)(sm + 2048);          // [128][16]
#pragma unroll
    for (int i = 0; i < 8; i++) {
        int m = mrow * 8 + i;
        rv[m * 16 + ncol] = bestv[i];
        ri[m * 16 + ncol] = besti[i];
    }
    __syncthreads();
    if (tid < 128) {
        int m = tid;
        float bv = rv[m * 16];
        int   bi = ri[m * 16];
#pragma unroll
        for (int t = 1; t < 16; t++) {
            float v = rv[m * 16 + t];
            int  id = ri[m * 16 + t];
            if (v < bv || (v == bv && id < bi)) { bv = v; bi = id; }
        }
        g_idx[bm0 + m] = bi;
        out_idx[bm0 + m] = (float)bi;
    }
}

// ---------------------------------------------------------------------------
// Fused: counts scatter, sum_embeddings scatter, z_q gather (straight-through
// rounding: z + (e - z)), commitment-loss partial sum.
// One thread per token (coalesced along t), loop over d.
__global__ void k_scatter_gather(const float* __restrict__ z,
                                 const float* __restrict__ emb,
                                 float* __restrict__ out_zq) {
    int tid   = threadIdx.x;
    int tok0  = blockIdx.x * 256;
    int b     = tok0 >> 11;
    int tl    = (tok0 & 2047) + tid;
    int token = tok0 + tid;
    int idx   = g_idx[token];
    atomicAdd(&g_counts[idx], 1.0f);

    const float* zb = z + (size_t)b * DIM * TLEN;
    float*       ob = out_zq + (size_t)b * DIM * TLEN;
    const float* er = emb + (size_t)idx * DIM;
    float* sr = g_sumemb + (size_t)idx * DIM;

    float lacc = 0.f;
#pragma unroll 4
    for (int d = 0; d < DIM; d++) {
        float zv = zb[(size_t)d * TLEN + tl];
        float ev = __ldg(er + d);
        ob[(size_t)d * TLEN + tl] = zv + (ev - zv);   // straight-through
        atomicAdd(sr + d, zv);
        float df = zv - ev;
        lacc = fmaf(df, df, lacc);
    }
#pragma unroll
    for (int o = 16; o; o >>= 1) lacc += __shfl_xor_sync(0xFFFFFFFFu, lacc, o);
    if ((tid & 31) == 0) atomicAdd(&g_scal[0], lacc);
}

// ---------------------------------------------------------------------------
// Single block: new_cluster_size, n = sum(ncs), utilization, loss.
__global__ void k_reduce(const float* __restrict__ cs,
                         float* __restrict__ out_ncs,
                         float* __restrict__ out_loss,
                         float* __restrict__ out_util) {
    __shared__ float sn[256];
    __shared__ float sz[256];
    int tid = threadIdx.x;
    const float om = (float)(1.0 - 0.99);   // matches Python (1.0 - DECAY) -> f32
    float nsum = 0.f, nz = 0.f;
    for (int k = tid; k < K_CODES; k += 256) {
        float c   = g_counts[k];
        float ncs = cs[k] * 0.99f + om * c;
        out_ncs[k] = ncs;
        nsum += ncs;
        nz += (c > 0.f) ? 1.f : 0.f;
    }
    sn[tid] = nsum; sz[tid] = nz;
    __syncthreads();
    for (int s = 128; s; s >>= 1) {
        if (tid < s) { sn[tid] += sn[tid + s]; sz[tid] += sz[tid + s]; }
        __syncthreads();
    }
    if (tid == 0) {
        g_scal[1] = sn[0];
        *out_loss = 1.0f * (g_scal[0] / (float)(NTOK * DIM));  // COMMIT_W * mean
        *out_util = sz[0] / (float)K_CODES;
    }
}

// ---------------------------------------------------------------------------
// Elementwise EMA update: new_embed_avg and new_embedding.
// Scalar stores (output offsets are not 16B aligned).
__global__ void k_update(const float* __restrict__ cs,
                         const float* __restrict__ ea,
                         float* __restrict__ out_nemb,
                         float* __restrict__ out_nea) {
    int gid = blockIdx.x * blockDim.x + threadIdx.x;   // element in [0, K*D)
    int k = gid >> 8;                                  // /DIM
    const float om = (float)(1.0 - 0.99);
    float n   = g_scal[1];
    float ncs = cs[k] * 0.99f + om * g_counts[k];
    float smoothed = (ncs + 1e-5f) / (n + (float)(K_CODES * 1e-5)) * n;
    float nav = ea[gid] * 0.99f + om * g_sumemb[gid];
    out_nea[gid]  = nav;
    out_nemb[gid] = nav / smoothed;
}

// ---------------------------------------------------------------------------
extern "C" void kernel_launch(void* const* d_in, const int* in_sizes, int n_in,
                              void* d_out, int out_size) {
    const float* z   = (const float*)d_in[0];   // (16, 256, 2048)
    const float* emb = (const float*)d_in[1];   // (8192, 256)
    const float* cs  = (const float*)d_in[2];   // (8192,)
    const float* ea  = (const float*)d_in[3];   // (8192, 256)
    float* out = (float*)d_out;

    float* o_zq   = out + OFF_ZQ;
    float* o_idx  = out + OFF_IDX;
    float* o_loss = out + OFF_LOSS;
    float* o_nemb = out + OFF_NEMB;
    float* o_ncs  = out + OFF_NCS;
    float* o_nea  = out + OFF_NEA;
    float* o_util = out + OFF_UTIL;

    k_init<<<2048, 256>>>();                       // zero scratch accumulators
    k_esq<<<K_CODES / 8, 256>>>(emb);              // code norms
    k_argmin<<<NTOK / 128, 256>>>(z, emb, o_idx);  // fused GEMM + argmin
    k_scatter_gather<<<NTOK / 256, 256>>>(z, emb, o_zq);
    k_reduce<<<1, 256>>>(cs, o_ncs, o_loss, o_util);
    k_update<<<K_CODES * DIM / 256, 256>>>(cs, ea, o_nemb, o_nea);
}